// round 8
// baseline (speedup 1.0000x reference)
#include <cuda_runtime.h>
#include <cstdint>

// Problem constants (fixed by the reference: B=8, H=16, L=512, D=64)
#define BH   128
#define LSEQ 512
#define DH   64
#define TQ   32     // q rows per block
#define TK   64     // k/v rows per smem tile
#define NTHR 256

#define QS_STRIDE  68           // %32==4 -> conflict-free fragment rows
#define S_STRIDE   516          // %32==4
#define SMEM_FLOATS (TQ * QS_STRIDE + 2 * TK * QS_STRIDE + TQ * S_STRIDE)
#define SMEM_BYTES  (SMEM_FLOATS * sizeof(float))   // ~107 KB -> 2 CTAs/SM

__device__ __forceinline__ uint32_t f2tf(float x) {
    uint32_t r;
    asm("cvt.rna.tf32.f32 %0, %1;" : "=r"(r) : "f"(x));
    return r;
}

__device__ __forceinline__ void mma_tf32(float d[4], const uint32_t a[4], const uint32_t b[2]) {
    asm volatile(
        "mma.sync.aligned.m16n8k8.row.col.f32.tf32.tf32.f32 "
        "{%0,%1,%2,%3}, {%4,%5,%6,%7}, {%8,%9}, {%0,%1,%2,%3};\n"
        : "+f"(d[0]), "+f"(d[1]), "+f"(d[2]), "+f"(d[3])
        : "r"(a[0]), "r"(a[1]), "r"(a[2]), "r"(a[3]), "r"(b[0]), "r"(b[1]));
}

// ldmatrix x4 on 32-bit data: matrix j -> lane L holds element [L/4][L%4] of an
// 8-row x 4-f32 tile whose row pointers come from lanes 8j..8j+7.
__device__ __forceinline__ void ldsm_x4(uint32_t& r0, uint32_t& r1,
                                        uint32_t& r2, uint32_t& r3, uint32_t addr) {
    asm volatile("ldmatrix.sync.aligned.m8n8.x4.shared.b16 {%0,%1,%2,%3}, [%4];"
                 : "=r"(r0), "=r"(r1), "=r"(r2), "=r"(r3) : "r"(addr));
}

__device__ __forceinline__ void cp_async16(void* smem_ptr, const void* gptr) {
    uint32_t s = (uint32_t)__cvta_generic_to_shared(smem_ptr);
    asm volatile("cp.async.cg.shared.global [%0], [%1], 16;" :: "r"(s), "l"(gptr));
}
#define CP_COMMIT()  asm volatile("cp.async.commit_group;")
#define CP_WAIT0()   asm volatile("cp.async.wait_group 0;")

__global__ __launch_bounds__(NTHR, 2)
void attn_fused_kernel(const float* __restrict__ q,
                       const float* __restrict__ k,
                       const float* __restrict__ v,
                       const float* __restrict__ sel,
                       const int* __restrict__ mask,
                       float* __restrict__ ctx,
                       float* __restrict__ attn)
{
    extern __shared__ float sm[];
    float (*Qs)[QS_STRIDE]    = (float (*)[QS_STRIDE])sm;                         // [32][68]
    float (*KV)[TK][QS_STRIDE]= (float (*)[TK][QS_STRIDE])(sm + TQ * QS_STRIDE);  // [2][64][68]
    float (*S)[S_STRIDE]      = (float (*)[S_STRIDE])(sm + TQ * QS_STRIDE + 2 * TK * QS_STRIDE); // [32][516]

    const int bh  = blockIdx.y;
    const int qt  = blockIdx.x;
    const int tid = threadIdx.x;
    const int warp = tid >> 5, lane = tid & 31;
    const int wm = warp & 1;           // 2 warps along M: rows wm*16..+15
    const int wn = warp >> 1;          // 4 warps along N: 16 cols each
    const int g  = lane >> 2;          // fragment group 0..7
    const int t  = lane & 3;           // fragment thread-in-group 0..3

    const float* qg = q + ((size_t)bh * LSEQ + (size_t)qt * TQ) * DH;
    const float* kg = k + (size_t)bh * LSEQ * DH;
    const float* vg = v + (size_t)bh * LSEQ * DH;

    // shared-address bases for ldmatrix
    const uint32_t smem_u32 = (uint32_t)__cvta_generic_to_shared(sm);
    const uint32_t kv_u32   = smem_u32 + TQ * QS_STRIDE * 4;
    const uint32_t s_u32    = smem_u32 + (TQ * QS_STRIDE + 2 * TK * QS_STRIDE) * 4;
    // per-thread ldmatrix row-pointer offsets
    // GEMM1 B (K tile): matrix j covers cols 4j..4j+3 of an 8-row block
    const uint32_t boff = (uint32_t)(((wn * 16 + (lane & 7)) * QS_STRIDE + 4 * (lane >> 3)) * 4);
    // GEMM3 A (S tile): m0/m1 rows wm*16+(lane&15), m2/m3 same rows cols +4
    const uint32_t aoff = (uint32_t)(((wm * 16 + (lane & 15)) * S_STRIDE + 4 * (lane >> 4)) * 4);

    // ---- prologue: async load Q tile + K tile 0 ----
    #pragma unroll
    for (int i = tid; i < TQ * DH / 4; i += NTHR) {
        int e = i * 4, r = e >> 6, c = e & 63;
        cp_async16(&Qs[r][c], qg + e);
    }
    #pragma unroll
    for (int i = tid; i < TK * DH / 4; i += NTHR) {
        int e = i * 4, r = e >> 6, c = e & 63;
        cp_async16(&KV[0][r][c], kg + e);
    }
    CP_COMMIT();
    CP_WAIT0();
    __syncthreads();

    // ---- hoist Q tf32 fragments, scale folded in (exact: 0.125 = 2^-3) ----
    uint32_t qa[DH / 8][4];
    #pragma unroll
    for (int ks = 0; ks < DH / 8; ++ks) {
        const int k0 = ks * 8;
        qa[ks][0] = f2tf(0.125f * Qs[wm * 16 + g    ][k0 + t    ]);
        qa[ks][1] = f2tf(0.125f * Qs[wm * 16 + g + 8][k0 + t    ]);
        qa[ks][2] = f2tf(0.125f * Qs[wm * 16 + g    ][k0 + t + 4]);
        qa[ks][3] = f2tf(0.125f * Qs[wm * 16 + g + 8][k0 + t + 4]);
    }

    // ---- phase 1: S = (Q*scale) @ K^T via tf32 mma ----
    for (int kt = 0; kt < LSEQ / TK; ++kt) {
        if (kt > 0) {
            CP_WAIT0();
            __syncthreads();
        }
        if (kt + 1 < LSEQ / TK) {
            const float* kn = kg + (size_t)(kt + 1) * TK * DH;
            #pragma unroll
            for (int i = tid; i < TK * DH / 4; i += NTHR) {
                int e = i * 4, r = e >> 6, c = e & 63;
                cp_async16(&KV[(kt + 1) & 1][r][c], kn + e);
            }
            CP_COMMIT();
        }

        // in-place tf32(rna) conversion of this K tile (own elements only)
        float (*Ks)[QS_STRIDE] = KV[kt & 1];
        #pragma unroll
        for (int j = 0; j < 4; ++j) {
            int e = (tid + j * NTHR) * 4, r = e >> 6, c = e & 63;
            float4 x = *(float4*)&Ks[r][c];
            x.x = __uint_as_float(f2tf(x.x));
            x.y = __uint_as_float(f2tf(x.y));
            x.z = __uint_as_float(f2tf(x.z));
            x.w = __uint_as_float(f2tf(x.w));
            *(float4*)&Ks[r][c] = x;
        }
        __syncthreads();   // converted tile visible to all fragment loads

        const uint32_t kbase = kv_u32 + (uint32_t)((kt & 1) * TK * QS_STRIDE * 4) + boff;
        float acc[2][4];
        #pragma unroll
        for (int nt = 0; nt < 2; ++nt)
            #pragma unroll
            for (int j = 0; j < 4; ++j) acc[nt][j] = 0.f;

        #pragma unroll
        for (int kb = 0; kb < 4; ++kb) {       // 16 k per block
            #pragma unroll
            for (int nt = 0; nt < 2; ++nt) {   // 8 n per block
                uint32_t b0, b1, b2, b3;
                ldsm_x4(b0, b1, b2, b3,
                        kbase + (uint32_t)((nt * 8 * QS_STRIDE + kb * 16) * 4));
                uint32_t blo[2] = {b0, b1};
                uint32_t bhi[2] = {b2, b3};
                mma_tf32(acc[nt], qa[2 * kb    ], blo);
                mma_tf32(acc[nt], qa[2 * kb + 1], bhi);
            }
        }

        #pragma unroll
        for (int nt = 0; nt < 2; ++nt) {
            const int n0 = kt * TK + wn * 16 + nt * 8 + 2 * t;
            S[wm * 16 + g    ][n0    ] = acc[nt][0];
            S[wm * 16 + g    ][n0 + 1] = acc[nt][1];
            S[wm * 16 + g + 8][n0    ] = acc[nt][2];
            S[wm * 16 + g + 8][n0 + 1] = acc[nt][3];
        }
    }

    // prefetch V tile 0 into buf 0 (overlaps softmax)
    #pragma unroll
    for (int i = tid; i < TK * DH / 4; i += NTHR) {
        int e = i * 4, r = e >> 6, c = e & 63;
        cp_async16(&KV[0][r][c], vg + e);
    }
    CP_COMMIT();
    __syncthreads();   // S complete for softmax

    // ---- phase 2: softmax, 4 rows per warp; attn fp32 out, S gets tf32 P ----
    {
        const size_t base = (size_t)bh * LSEQ * LSEQ + (size_t)qt * TQ * LSEQ;
        const float* selp = sel + base;
        const int* mp = mask + base;
        float* attnp = attn + base;

        #pragma unroll
        for (int rr = 0; rr < 4; ++rr) {
            const int r = warp * 4 + rr;
            float vals[16];
            float lmax = -1e30f;
            #pragma unroll
            for (int i = 0; i < 4; ++i) {
                const int c = i * 128 + lane * 4;
                float4 sv = *(const float4*)&S[r][c];
                float4 se = *(const float4*)&selp[(size_t)r * LSEQ + c];
                int4  mv = *(const int4*)&mp[(size_t)r * LSEQ + c];
                float x0 = sv.x + se.x; if (mv.x == 0) x0 = -1e12f;
                float x1 = sv.y + se.y; if (mv.y == 0) x1 = -1e12f;
                float x2 = sv.z + se.z; if (mv.z == 0) x2 = -1e12f;
                float x3 = sv.w + se.w; if (mv.w == 0) x3 = -1e12f;
                vals[4 * i + 0] = x0; vals[4 * i + 1] = x1;
                vals[4 * i + 2] = x2; vals[4 * i + 3] = x3;
                lmax = fmaxf(lmax, fmaxf(fmaxf(x0, x1), fmaxf(x2, x3)));
            }
            #pragma unroll
            for (int o = 16; o > 0; o >>= 1)
                lmax = fmaxf(lmax, __shfl_xor_sync(0xffffffffu, lmax, o));
            float lsum = 0.f;
            #pragma unroll
            for (int i = 0; i < 16; ++i) {
                vals[i] = __expf(vals[i] - lmax);
                lsum += vals[i];
            }
            #pragma unroll
            for (int o = 16; o > 0; o >>= 1)
                lsum += __shfl_xor_sync(0xffffffffu, lsum, o);
            const float inv = 1.0f / lsum;
            #pragma unroll
            for (int i = 0; i < 4; ++i) {
                const int c = i * 128 + lane * 4;
                float4 a4;
                a4.x = vals[4 * i + 0] * inv;
                a4.y = vals[4 * i + 1] * inv;
                a4.z = vals[4 * i + 2] * inv;
                a4.w = vals[4 * i + 3] * inv;
                __stcs((float4*)&attnp[(size_t)r * LSEQ + c], a4);  // fp32 out, streaming
                float4 p4;                                           // tf32-pre-rounded for PV
                p4.x = __uint_as_float(f2tf(a4.x));
                p4.y = __uint_as_float(f2tf(a4.y));
                p4.z = __uint_as_float(f2tf(a4.z));
                p4.w = __uint_as_float(f2tf(a4.w));
                *(float4*)&S[r][c] = p4;
            }
        }
    }
    __syncthreads();

    // ---- phase 3: ctx = P(S) @ V via tf32 mma ----
    {
        float acc[2][4];
        #pragma unroll
        for (int nt = 0; nt < 2; ++nt)
            #pragma unroll
            for (int j = 0; j < 4; ++j) acc[nt][j] = 0.f;

        for (int vt = 0; vt < LSEQ / TK; ++vt) {
            CP_WAIT0();
            __syncthreads();
            if (vt + 1 < LSEQ / TK) {
                const float* vn = vg + (size_t)(vt + 1) * TK * DH;
                #pragma unroll
                for (int i = tid; i < TK * DH / 4; i += NTHR) {
                    int e = i * 4, r = e >> 6, c = e & 63;
                    cp_async16(&KV[(vt + 1) & 1][r][c], vn + e);
                }
                CP_COMMIT();
            }

            // in-place tf32(rna) conversion of this V tile
            float (*Vs)[QS_STRIDE] = KV[vt & 1];
            #pragma unroll
            for (int j = 0; j < 4; ++j) {
                int e = (tid + j * NTHR) * 4, r = e >> 6, c = e & 63;
                float4 x = *(float4*)&Vs[r][c];
                x.x = __uint_as_float(f2tf(x.x));
                x.y = __uint_as_float(f2tf(x.y));
                x.z = __uint_as_float(f2tf(x.z));
                x.w = __uint_as_float(f2tf(x.w));
                *(float4*)&Vs[r][c] = x;
            }
            __syncthreads();

            #pragma unroll
            for (int ks = 0; ks < TK / 8; ++ks) {
                const int sk = vt * TK + ks * 8;   // S column (k index)
                const int vk = ks * 8;             // V smem row
                uint32_t a[4];                     // P fragments via ldmatrix
                ldsm_x4(a[0], a[1], a[2], a[3], s_u32 + aoff + (uint32_t)(sk * 4));
                #pragma unroll
                for (int nt = 0; nt < 2; ++nt) {
                    const int n0 = wn * 16 + nt * 8;
                    uint32_t b[2];                 // V pre-converted: raw bits
                    b[0] = __float_as_uint(Vs[vk + t    ][n0 + g]);
                    b[1] = __float_as_uint(Vs[vk + t + 4][n0 + g]);
                    mma_tf32(acc[nt], a, b);
                }
            }
        }

        float* cp = ctx + ((size_t)bh * LSEQ + (size_t)qt * TQ) * DH;
        #pragma unroll
        for (int nt = 0; nt < 2; ++nt) {
            const int n0 = wn * 16 + nt * 8 + 2 * t;
            __stcs((float2*)&cp[(size_t)(wm * 16 + g    ) * DH + n0],
                   make_float2(acc[nt][0], acc[nt][1]));
            __stcs((float2*)&cp[(size_t)(wm * 16 + g + 8) * DH + n0],
                   make_float2(acc[nt][2], acc[nt][3]));
        }
    }
}

extern "C" void kernel_launch(void* const* d_in, const int* in_sizes, int n_in,
                              void* d_out, int out_size)
{
    (void)in_sizes; (void)n_in; (void)out_size;
    const float* q = (const float*)d_in[0];
    const float* k = (const float*)d_in[1];
    const float* v = (const float*)d_in[2];
    const float* sel = (const float*)d_in[3];
    const int* mask = (const int*)d_in[4];

    float* ctx  = (float*)d_out;                          // [128,512,64]
    float* attn = ctx + (size_t)BH * LSEQ * DH;           // [128,512,512]

    cudaFuncSetAttribute(attn_fused_kernel,
                         cudaFuncAttributeMaxDynamicSharedMemorySize, (int)SMEM_BYTES);

    dim3 grid(LSEQ / TQ, BH);   // (16, 128) = 2048 blocks
    attn_fused_kernel<<<grid, NTHR, SMEM_BYTES>>>(q, k, v, sel, mask, ctx, attn);
}

// round 9
// speedup vs baseline: 1.1307x; 1.1307x over previous
#include <cuda_runtime.h>
#include <cstdint>

// Problem constants (fixed by the reference: B=8, H=16, L=512, D=64)
#define BH   128
#define LSEQ 512
#define DH   64
#define TQ   64     // q rows per block
#define TK   64     // k/v rows per smem tile
#define NTHR 512

#define QS_STRIDE  68           // %32==4 -> conflict-free fragment rows
#define S_STRIDE   516          // %32==4
#define SMEM_FLOATS (TQ * QS_STRIDE + 2 * TK * QS_STRIDE + TQ * S_STRIDE)
#define SMEM_BYTES  (SMEM_FLOATS * sizeof(float))

__device__ __forceinline__ uint32_t f2tf(float x) {
    uint32_t r;
    asm("cvt.rna.tf32.f32 %0, %1;" : "=r"(r) : "f"(x));
    return r;
}
__device__ __forceinline__ uint32_t f2tf_bits(uint32_t xb) {
    uint32_t r;
    asm("cvt.rna.tf32.f32 %0, %1;" : "=r"(r) : "f"(__uint_as_float(xb)));
    return r;
}

__device__ __forceinline__ void mma_tf32(float d[4], const uint32_t a[4], const uint32_t b[2]) {
    asm volatile(
        "mma.sync.aligned.m16n8k8.row.col.f32.tf32.tf32.f32 "
        "{%0,%1,%2,%3}, {%4,%5,%6,%7}, {%8,%9}, {%0,%1,%2,%3};\n"
        : "+f"(d[0]), "+f"(d[1]), "+f"(d[2]), "+f"(d[3])
        : "r"(a[0]), "r"(a[1]), "r"(a[2]), "r"(a[3]), "r"(b[0]), "r"(b[1]));
}

// ldmatrix x4 on 32-bit data: matrix j -> lane L holds element [L/4][L%4] of an
// 8-row x 4-f32 tile whose row pointers come from lanes 8j..8j+7.
// (fragment mapping verified correct on-chip in round 7: rel_err identical)
__device__ __forceinline__ void ldsm_x4(uint32_t& r0, uint32_t& r1,
                                        uint32_t& r2, uint32_t& r3, uint32_t addr) {
    asm volatile("ldmatrix.sync.aligned.m8n8.x4.shared.b16 {%0,%1,%2,%3}, [%4];"
                 : "=r"(r0), "=r"(r1), "=r"(r2), "=r"(r3) : "r"(addr));
}

__device__ __forceinline__ void cp_async16(void* smem_ptr, const void* gptr) {
    uint32_t s = (uint32_t)__cvta_generic_to_shared(smem_ptr);
    asm volatile("cp.async.cg.shared.global [%0], [%1], 16;" :: "r"(s), "l"(gptr));
}
#define CP_COMMIT()  asm volatile("cp.async.commit_group;")
#define CP_WAIT0()   asm volatile("cp.async.wait_group 0;")

__global__ __launch_bounds__(NTHR, 1)
void attn_fused_kernel(const float* __restrict__ q,
                       const float* __restrict__ k,
                       const float* __restrict__ v,
                       const float* __restrict__ sel,
                       const int* __restrict__ mask,
                       float* __restrict__ ctx,
                       float* __restrict__ attn)
{
    extern __shared__ float sm[];
    float (*Qs)[QS_STRIDE]    = (float (*)[QS_STRIDE])sm;                         // [64][68]
    float (*KV)[TK][QS_STRIDE]= (float (*)[TK][QS_STRIDE])(sm + TQ * QS_STRIDE);  // [2][64][68]
    float (*S)[S_STRIDE]      = (float (*)[S_STRIDE])(sm + TQ * QS_STRIDE + 2 * TK * QS_STRIDE); // [64][516]

    const int bh  = blockIdx.y;
    const int qt  = blockIdx.x;
    const int tid = threadIdx.x;
    const int warp = tid >> 5, lane = tid & 31;
    const int wm = warp & 3;           // 4 warps along M: rows wm*16..+15
    const int wn = warp >> 2;          // 4 warps along N: 16 cols each
    const int g  = lane >> 2;          // fragment group 0..7
    const int t  = lane & 3;           // fragment thread-in-group 0..3

    const float* qg = q + ((size_t)bh * LSEQ + (size_t)qt * TQ) * DH;
    const float* kg = k + (size_t)bh * LSEQ * DH;
    const float* vg = v + (size_t)bh * LSEQ * DH;

    // shared-address bases for ldmatrix
    const uint32_t smem_u32 = (uint32_t)__cvta_generic_to_shared(sm);
    const uint32_t kv_u32   = smem_u32 + TQ * QS_STRIDE * 4;
    const uint32_t s_u32    = smem_u32 + (TQ * QS_STRIDE + 2 * TK * QS_STRIDE) * 4;
    // GEMM1 B (K tile): 4 matrices = rows[wn*16+nt*8 .. +7] x cols[kb*16 .. +15]
    const uint32_t boff = (uint32_t)(((wn * 16 + (lane & 7)) * QS_STRIDE + 4 * (lane >> 3)) * 4);
    // GEMM3 A (S tile): 4 matrices = rows[wm*16+(lane&15)] cols[+4*(lane>>4)]
    const uint32_t aoff = (uint32_t)(((wm * 16 + (lane & 15)) * S_STRIDE + 4 * (lane >> 4)) * 4);

    // ---- prologue: async load Q tile + K tile 0 ----
    #pragma unroll
    for (int i = tid; i < TQ * DH / 4; i += NTHR) {
        int e = i * 4, r = e >> 6, c = e & 63;
        cp_async16(&Qs[r][c], qg + e);
        cp_async16(&KV[0][r][c], kg + e);
    }
    CP_COMMIT();
    CP_WAIT0();
    __syncthreads();

    // ---- hoist Q tf32 fragments, scale folded in (exact: 0.125 = 2^-3) ----
    uint32_t qa[DH / 8][4];
    #pragma unroll
    for (int ks = 0; ks < DH / 8; ++ks) {
        const int k0 = ks * 8;
        qa[ks][0] = f2tf(0.125f * Qs[wm * 16 + g    ][k0 + t    ]);
        qa[ks][1] = f2tf(0.125f * Qs[wm * 16 + g + 8][k0 + t    ]);
        qa[ks][2] = f2tf(0.125f * Qs[wm * 16 + g    ][k0 + t + 4]);
        qa[ks][3] = f2tf(0.125f * Qs[wm * 16 + g + 8][k0 + t + 4]);
    }

    // ---- phase 1: S = (Q*scale) @ K^T via tf32 mma, double-buffered K ----
    for (int kt = 0; kt < LSEQ / TK; ++kt) {
        if (kt > 0) {
            CP_WAIT0();
            __syncthreads();
        }
        if (kt + 1 < LSEQ / TK) {
            const float* kn = kg + (size_t)(kt + 1) * TK * DH;
            #pragma unroll
            for (int i = tid; i < TK * DH / 4; i += NTHR) {
                int e = i * 4, r = e >> 6, c = e & 63;
                cp_async16(&KV[(kt + 1) & 1][r][c], kn + e);
            }
            CP_COMMIT();
        }

        const uint32_t kbase = kv_u32 + (uint32_t)((kt & 1) * TK * QS_STRIDE * 4) + boff;
        float acc[2][4];
        #pragma unroll
        for (int nt = 0; nt < 2; ++nt)
            #pragma unroll
            for (int j = 0; j < 4; ++j) acc[nt][j] = 0.f;

        #pragma unroll
        for (int kb = 0; kb < 4; ++kb) {       // 16 k per block (2 k-steps)
            #pragma unroll
            for (int nt = 0; nt < 2; ++nt) {
                uint32_t b0, b1, b2, b3;
                ldsm_x4(b0, b1, b2, b3,
                        kbase + (uint32_t)((nt * 8 * QS_STRIDE + kb * 16) * 4));
                uint32_t blo[2] = {f2tf_bits(b0), f2tf_bits(b1)};
                uint32_t bhi[2] = {f2tf_bits(b2), f2tf_bits(b3)};
                mma_tf32(acc[nt], qa[2 * kb    ], blo);
                mma_tf32(acc[nt], qa[2 * kb + 1], bhi);
            }
        }

        #pragma unroll
        for (int nt = 0; nt < 2; ++nt) {
            const int n0 = kt * TK + wn * 16 + nt * 8 + 2 * t;
            S[wm * 16 + g    ][n0    ] = acc[nt][0];
            S[wm * 16 + g    ][n0 + 1] = acc[nt][1];
            S[wm * 16 + g + 8][n0    ] = acc[nt][2];
            S[wm * 16 + g + 8][n0 + 1] = acc[nt][3];
        }
    }

    // prefetch V tile 0 into buf 0 (overlaps softmax); buf0 last read at kt=6,
    // whose consumers all passed the kt=7 top barrier.
    #pragma unroll
    for (int i = tid; i < TK * DH / 4; i += NTHR) {
        int e = i * 4, r = e >> 6, c = e & 63;
        cp_async16(&KV[0][r][c], vg + e);
    }
    CP_COMMIT();
    __syncthreads();   // S complete for softmax

    // ---- phase 2: softmax, 4 rows per warp; attn fp32 out, S gets tf32 P ----
    {
        const size_t base = (size_t)bh * LSEQ * LSEQ + (size_t)qt * TQ * LSEQ;
        const float* selp = sel + base;
        const int* mp = mask + base;
        float* attnp = attn + base;

        #pragma unroll
        for (int rr = 0; rr < 4; ++rr) {
            const int r = warp * 4 + rr;
            float vals[16];
            float lmax = -1e30f;
            #pragma unroll
            for (int i = 0; i < 4; ++i) {
                const int c = i * 128 + lane * 4;
                float4 sv = *(const float4*)&S[r][c];
                float4 se = *(const float4*)&selp[(size_t)r * LSEQ + c];
                int4  mv = *(const int4*)&mp[(size_t)r * LSEQ + c];
                float x0 = sv.x + se.x; if (mv.x == 0) x0 = -1e12f;
                float x1 = sv.y + se.y; if (mv.y == 0) x1 = -1e12f;
                float x2 = sv.z + se.z; if (mv.z == 0) x2 = -1e12f;
                float x3 = sv.w + se.w; if (mv.w == 0) x3 = -1e12f;
                vals[4 * i + 0] = x0; vals[4 * i + 1] = x1;
                vals[4 * i + 2] = x2; vals[4 * i + 3] = x3;
                lmax = fmaxf(lmax, fmaxf(fmaxf(x0, x1), fmaxf(x2, x3)));
            }
            #pragma unroll
            for (int o = 16; o > 0; o >>= 1)
                lmax = fmaxf(lmax, __shfl_xor_sync(0xffffffffu, lmax, o));
            float lsum = 0.f;
            #pragma unroll
            for (int i = 0; i < 16; ++i) {
                vals[i] = __expf(vals[i] - lmax);
                lsum += vals[i];
            }
            #pragma unroll
            for (int o = 16; o > 0; o >>= 1)
                lsum += __shfl_xor_sync(0xffffffffu, lsum, o);
            const float inv = 1.0f / lsum;
            #pragma unroll
            for (int i = 0; i < 4; ++i) {
                const int c = i * 128 + lane * 4;
                float4 a4;
                a4.x = vals[4 * i + 0] * inv;
                a4.y = vals[4 * i + 1] * inv;
                a4.z = vals[4 * i + 2] * inv;
                a4.w = vals[4 * i + 3] * inv;
                *(float4*)&attnp[(size_t)r * LSEQ + c] = a4;   // full precision out
                float4 p4;                                      // tf32-pre-rounded for PV
                p4.x = __uint_as_float(f2tf(a4.x));
                p4.y = __uint_as_float(f2tf(a4.y));
                p4.z = __uint_as_float(f2tf(a4.z));
                p4.w = __uint_as_float(f2tf(a4.w));
                *(float4*)&S[r][c] = p4;
            }
        }
    }
    __syncthreads();

    // ---- phase 3: ctx = P(S) @ V via tf32 mma, double-buffered V ----
    {
        float acc[2][4];
        #pragma unroll
        for (int nt = 0; nt < 2; ++nt)
            #pragma unroll
            for (int j = 0; j < 4; ++j) acc[nt][j] = 0.f;

        for (int vt = 0; vt < LSEQ / TK; ++vt) {
            CP_WAIT0();
            __syncthreads();
            if (vt + 1 < LSEQ / TK) {
                const float* vn = vg + (size_t)(vt + 1) * TK * DH;
                #pragma unroll
                for (int i = tid; i < TK * DH / 4; i += NTHR) {
                    int e = i * 4, r = e >> 6, c = e & 63;
                    cp_async16(&KV[(vt + 1) & 1][r][c], vn + e);
                }
                CP_COMMIT();
            }

            float (*Vs)[QS_STRIDE] = KV[vt & 1];
            #pragma unroll
            for (int ks = 0; ks < TK / 8; ++ks) {
                const int sk = vt * TK + ks * 8;   // S column (k index)
                const int vk = ks * 8;             // V smem row
                uint32_t a[4];                     // P pre-rounded: ldmatrix raw bits
                ldsm_x4(a[0], a[1], a[2], a[3], s_u32 + aoff + (uint32_t)(sk * 4));
                #pragma unroll
                for (int nt = 0; nt < 2; ++nt) {
                    const int n0 = wn * 16 + nt * 8;
                    uint32_t b[2];
                    b[0] = f2tf(Vs[vk + t    ][n0 + g]);
                    b[1] = f2tf(Vs[vk + t + 4][n0 + g]);
                    mma_tf32(acc[nt], a, b);
                }
            }
            __syncthreads();   // buf[vt&1] free for prefetch vt+2
        }

        float* cp = ctx + ((size_t)bh * LSEQ + (size_t)qt * TQ) * DH;
        #pragma unroll
        for (int nt = 0; nt < 2; ++nt) {
            const int n0 = wn * 16 + nt * 8 + 2 * t;
            float2 lo = make_float2(acc[nt][0], acc[nt][1]);
            float2 hi = make_float2(acc[nt][2], acc[nt][3]);
            *(float2*)&cp[(size_t)(wm * 16 + g    ) * DH + n0] = lo;
            *(float2*)&cp[(size_t)(wm * 16 + g + 8) * DH + n0] = hi;
        }
    }
}

extern "C" void kernel_launch(void* const* d_in, const int* in_sizes, int n_in,
                              void* d_out, int out_size)
{
    (void)in_sizes; (void)n_in; (void)out_size;
    const float* q = (const float*)d_in[0];
    const float* k = (const float*)d_in[1];
    const float* v = (const float*)d_in[2];
    const float* sel = (const float*)d_in[3];
    const int* mask = (const int*)d_in[4];

    float* ctx  = (float*)d_out;                          // [128,512,64]
    float* attn = ctx + (size_t)BH * LSEQ * DH;           // [128,512,512]

    cudaFuncSetAttribute(attn_fused_kernel,
                         cudaFuncAttributeMaxDynamicSharedMemorySize, (int)SMEM_BYTES);

    dim3 grid(LSEQ / TQ, BH);   // (8, 128) = 1024 blocks
    attn_fused_kernel<<<grid, NTHR, SMEM_BYTES>>>(q, k, v, sel, mask, ctx, attn);
}